// round 3
// baseline (speedup 1.0000x reference)
#include <cuda_runtime.h>
#include <cuda_bf16.h>
#include <cstdint>

// Problem dims (fixed by the reference)
#define VOCAB 50000
#define EDIM  64
#define HDIM  64
#define BATCH 1024
#define SEQ   512

// Scratch: projected table proj[v][h] = b_ih[h]+b_hh[h] + sum_e emb[v,e]*W_ih[h,e]
__device__ float g_proj[VOCAB * HDIM];   // 12.8 MB, L2-resident in steady state
__device__ int   g_x64flag;              // 1 if token buffer is int64, 0 if int32

// Fast tanh: tanh(x) = 1 - 2/(1 + exp(2x)). ex2.approx + rcp.approx,
// rel err ~1e-6 (vs ~6e-4 for tanh.approx.f32, which would risk the 1e-3 gate).
__device__ __forceinline__ float fast_tanh(float x) {
    float e, r;
    asm("ex2.approx.f32 %0, %1;" : "=f"(e) : "f"(x * 2.885390081777927f)); // 2/ln2
    asm("rcp.approx.f32 %0, %1;" : "=f"(r) : "f"(e + 1.0f));
    return fmaf(-2.0f, r, 1.0f);
}

#define FMA2(acc, a, b) asm("fma.rn.f32x2 %0, %1, %2, %0;" : "+l"(acc) : "l"(a), "l"(b))
#define ADD2(acc, b)    asm("add.rn.f32x2 %0, %0, %1;"     : "+l"(acc) : "l"(b))

// ---------------------------------------------------------------------------
// Kernel A: build projected embedding table (fuses gather-side GEMM + biases).
// Block 0 warp 0 additionally detects int32-vs-int64 token layout: tokens are
// in [0,50000), so for little-endian int64 every odd 32-bit word is 0.
// ---------------------------------------------------------------------------
#define PROJ_ROWS 32
__global__ __launch_bounds__(256) void proj_kernel(
    const int*   __restrict__ x32,
    const float* __restrict__ emb,
    const float* __restrict__ W_ih,
    const float* __restrict__ b_ih,
    const float* __restrict__ b_hh)
{
    __shared__ float s_w[HDIM * 65];
    __shared__ float s_e[PROJ_ROWS * EDIM];
    __shared__ float s_bias[HDIM];

    const int t  = threadIdx.x;
    const int v0 = blockIdx.x * PROJ_ROWS;

    // Token-layout probe: 32 lanes each check one odd word, ballot.
    if (blockIdx.x == 0 && t < 32) {
        unsigned m = __ballot_sync(0xffffffff, x32[2 * t + 1] != 0);
        if (t == 0) g_x64flag = (m == 0u) ? 1 : 0;
    }

    #pragma unroll
    for (int k = 0; k < 16; k++) {
        int idx = t + k * 256;                 // 0..4095
        int hg = idx >> 6, eg = idx & 63;
        s_w[hg * 65 + eg] = W_ih[idx];
    }
    #pragma unroll
    for (int k = 0; k < 8; k++) {
        int idx = t + k * 256;                 // 0..2047
        int r = idx >> 6, e = idx & 63;
        s_e[idx] = (v0 + r < VOCAB) ? emb[(long)(v0 + r) * EDIM + e] : 0.0f;
    }
    if (t < HDIM) s_bias[t] = b_ih[t] + b_hh[t];
    __syncthreads();

    const int h    = t & 63;
    const int rgrp = t >> 6;                   // 0..3
    #pragma unroll
    for (int k = 0; k < 8; k++) {
        int r = rgrp + 4 * k;                  // 0..31
        if (v0 + r >= VOCAB) break;
        float acc = s_bias[h];
        #pragma unroll
        for (int e = 0; e < EDIM; e++)
            acc += s_e[r * EDIM + e] * s_w[h * 65 + e];
        g_proj[(v0 + r) * HDIM + h] = acc;
    }
}

// ---------------------------------------------------------------------------
// Kernel B: recurrence + fc + sigmoid, TWO batch rows per block via packed
// fma.rn.f32x2 (FFMA2). 64 threads/block; thread i owns h[i] of both rows.
// W_hh row i duplicated into 64 packed 64-bit regs. h broadcast through
// double-buffered smem as float2 pairs (LDS.128 via ulonglong2).
// 8 accumulators -> FFMA2 chain depth 8 (32 cyc serial).
// ---------------------------------------------------------------------------
__global__ __launch_bounds__(64) void rnn2_kernel(
    const int*   __restrict__ x32,
    const float* __restrict__ W_hh,
    const float* __restrict__ fc_w,
    const float* __restrict__ fc_b,
    float*       __restrict__ out)
{
    __shared__ int    s_tok[2][SEQ];
    __shared__ float2 s_h[2][HDIM];
    __shared__ float2 s_part[2];

    const int bp = blockIdx.x;            // 0..511
    const int b0 = 2 * bp, b1 = 2 * bp + 1;
    const int i  = threadIdx.x;
    const int flag = g_x64flag;

    // Preload both rows' tokens (handles int32 or int64 source layout)
    for (int t = i; t < SEQ; t += 64) {
        long baseA = (long)b0 * SEQ + t;
        long baseB = (long)b1 * SEQ + t;
        s_tok[0][t] = flag ? x32[2 * baseA] : x32[baseA];
        s_tok[1][t] = flag ? x32[2 * baseB] : x32[baseB];
    }

    // W_hh row i, each weight duplicated into a packed (w,w) 64-bit register
    unsigned long long wp[HDIM];
    {
        const float4* w4 = (const float4*)(W_hh + i * HDIM);
        #pragma unroll
        for (int q = 0; q < 16; q++) {
            float4 v = w4[q];
            asm("mov.b64 %0, {%1, %1};" : "=l"(wp[4 * q + 0]) : "f"(v.x));
            asm("mov.b64 %0, {%1, %1};" : "=l"(wp[4 * q + 1]) : "f"(v.y));
            asm("mov.b64 %0, {%1, %1};" : "=l"(wp[4 * q + 2]) : "f"(v.z));
            asm("mov.b64 %0, {%1, %1};" : "=l"(wp[4 * q + 3]) : "f"(v.w));
        }
    }

    s_h[0][i] = make_float2(0.0f, 0.0f);
    __syncthreads();

    float xpA = g_proj[s_tok[0][0] * HDIM + i];
    float xpB = g_proj[s_tok[1][0] * HDIM + i];
    float hA = 0.0f, hB = 0.0f;

    #pragma unroll 1
    for (int t = 0; t < SEQ; t++) {
        unsigned long long acc[8];
        asm("mov.b64 %0, {%1, %2};" : "=l"(acc[0]) : "f"(xpA), "f"(xpB));
        #pragma unroll
        for (int k = 1; k < 8; k++) acc[k] = 0ULL;

        // Prefetch next step's projected rows (wraps harmlessly at t=511)
        int tn = (t + 1) & (SEQ - 1);
        xpA = g_proj[s_tok[0][tn] * HDIM + i];
        xpB = g_proj[s_tok[1][tn] * HDIM + i];

        const ulonglong2* hs2 = (const ulonglong2*)s_h[t & 1];
        #pragma unroll
        for (int j = 0; j < 32; j += 4) {       // 32 ulonglong2 = 64 packed h pairs
            ulonglong2 p0 = hs2[j + 0];
            ulonglong2 p1 = hs2[j + 1];
            ulonglong2 p2 = hs2[j + 2];
            ulonglong2 p3 = hs2[j + 3];
            FMA2(acc[0], p0.x, wp[2 * j + 0]);
            FMA2(acc[1], p0.y, wp[2 * j + 1]);
            FMA2(acc[2], p1.x, wp[2 * j + 2]);
            FMA2(acc[3], p1.y, wp[2 * j + 3]);
            FMA2(acc[4], p2.x, wp[2 * j + 4]);
            FMA2(acc[5], p2.y, wp[2 * j + 5]);
            FMA2(acc[6], p3.x, wp[2 * j + 6]);
            FMA2(acc[7], p3.y, wp[2 * j + 7]);
        }
        ADD2(acc[0], acc[1]); ADD2(acc[2], acc[3]);
        ADD2(acc[4], acc[5]); ADD2(acc[6], acc[7]);
        ADD2(acc[0], acc[2]); ADD2(acc[4], acc[6]);
        ADD2(acc[0], acc[4]);

        float aA, aB;
        asm("mov.b64 {%0, %1}, %2;" : "=f"(aA), "=f"(aB) : "l"(acc[0]));
        hA = fast_tanh(aA);
        hB = fast_tanh(aB);
        s_h[(t & 1) ^ 1][i] = make_float2(hA, hB);
        __syncthreads();
    }

    // fc + sigmoid for both rows
    float f = fc_w[i];
    float vA = hA * f, vB = hB * f;
    #pragma unroll
    for (int off = 16; off; off >>= 1) {
        vA += __shfl_xor_sync(0xffffffff, vA, off);
        vB += __shfl_xor_sync(0xffffffff, vB, off);
    }
    if ((i & 31) == 0) s_part[i >> 5] = make_float2(vA, vB);
    __syncthreads();
    if (i == 0) {
        float bias = fc_b[0];
        float lA = s_part[0].x + s_part[1].x + bias;
        float lB = s_part[0].y + s_part[1].y + bias;
        out[b0] = 1.0f / (1.0f + expf(-lA));
        out[b1] = 1.0f / (1.0f + expf(-lB));
    }
}

// ---------------------------------------------------------------------------
// Launch. Inputs (metadata order): x, emb, W_ih, W_hh, b_ih, b_hh, fc_w, fc_b
// 2 launches/call so ncu -s 5 -c 1 lands on rnn2_kernel.
// ---------------------------------------------------------------------------
extern "C" void kernel_launch(void* const* d_in, const int* in_sizes, int n_in,
                              void* d_out, int out_size)
{
    const int*   x32  = (const int*)  d_in[0];
    const float* emb  = (const float*)d_in[1];
    const float* W_ih = (const float*)d_in[2];
    const float* W_hh = (const float*)d_in[3];
    const float* b_ih = (const float*)d_in[4];
    const float* b_hh = (const float*)d_in[5];
    const float* fc_w = (const float*)d_in[6];
    const float* fc_b = (const float*)d_in[7];
    float* out = (float*)d_out;

    proj_kernel<<<(VOCAB + PROJ_ROWS - 1) / PROJ_ROWS, 256>>>(x32, emb, W_ih, b_ih, b_hh);
    rnn2_kernel<<<BATCH / 2, 64>>>(x32, W_hh, fc_w, fc_b, out);
}

// round 4
// speedup vs baseline: 1.1603x; 1.1603x over previous
#include <cuda_runtime.h>
#include <cuda_bf16.h>
#include <cstdint>

// Problem dims (fixed by the reference)
#define VOCAB 50000
#define EDIM  64
#define HDIM  64
#define BATCH 1024
#define SEQ   512

// Scratch: projected table proj[v][h] = b_ih[h]+b_hh[h] + sum_e emb[v,e]*W_ih[h,e]
__device__ float g_proj[VOCAB * HDIM];   // 12.8 MB, L2-resident in steady state
__device__ int   g_x64flag;              // 1 if token buffer is int64, 0 if int32

// Fast tanh: tanh(x) = 1 - 2/(1 + exp(2x)). ex2.approx + rcp.approx,
// rel err ~1e-6 (vs ~6e-4 for tanh.approx.f32, which would risk the 1e-3 gate).
__device__ __forceinline__ float fast_tanh(float x) {
    float e, r;
    asm("ex2.approx.f32 %0, %1;" : "=f"(e) : "f"(x * 2.885390081777927f)); // 2/ln2
    asm("rcp.approx.f32 %0, %1;" : "=f"(r) : "f"(e + 1.0f));
    return fmaf(-2.0f, r, 1.0f);
}

#define FMA2(acc, a, b) asm("fma.rn.f32x2 %0, %1, %2, %0;" : "+l"(acc) : "l"(a), "l"(b))
#define ADD2(acc, b)    asm("add.rn.f32x2 %0, %0, %1;"     : "+l"(acc) : "l"(b))

// ---------------------------------------------------------------------------
// Kernel A: build projected embedding table (fuses gather-side GEMM + biases).
// Block 0 warp 0 additionally detects int32-vs-int64 token layout: tokens are
// in [0,50000), so for little-endian int64 every odd 32-bit word is 0.
// ---------------------------------------------------------------------------
#define PROJ_ROWS 32
__global__ __launch_bounds__(256) void proj_kernel(
    const int*   __restrict__ x32,
    const float* __restrict__ emb,
    const float* __restrict__ W_ih,
    const float* __restrict__ b_ih,
    const float* __restrict__ b_hh)
{
    __shared__ float s_w[HDIM * 65];
    __shared__ float s_e[PROJ_ROWS * EDIM];
    __shared__ float s_bias[HDIM];

    const int t  = threadIdx.x;
    const int v0 = blockIdx.x * PROJ_ROWS;

    if (blockIdx.x == 0 && t < 32) {
        unsigned m = __ballot_sync(0xffffffff, x32[2 * t + 1] != 0);
        if (t == 0) g_x64flag = (m == 0u) ? 1 : 0;
    }

    #pragma unroll
    for (int k = 0; k < 16; k++) {
        int idx = t + k * 256;                 // 0..4095
        int hg = idx >> 6, eg = idx & 63;
        s_w[hg * 65 + eg] = W_ih[idx];
    }
    #pragma unroll
    for (int k = 0; k < 8; k++) {
        int idx = t + k * 256;                 // 0..2047
        int r = idx >> 6, e = idx & 63;
        s_e[idx] = (v0 + r < VOCAB) ? emb[(long)(v0 + r) * EDIM + e] : 0.0f;
    }
    if (t < HDIM) s_bias[t] = b_ih[t] + b_hh[t];
    __syncthreads();

    const int h    = t & 63;
    const int rgrp = t >> 6;                   // 0..3
    #pragma unroll
    for (int k = 0; k < 8; k++) {
        int r = rgrp + 4 * k;                  // 0..31
        if (v0 + r >= VOCAB) break;
        float acc = s_bias[h];
        #pragma unroll
        for (int e = 0; e < EDIM; e++)
            acc += s_e[r * EDIM + e] * s_w[h * 65 + e];
        g_proj[(v0 + r) * HDIM + h] = acc;
    }
}

// ---------------------------------------------------------------------------
// Kernel B: recurrence + fc + sigmoid. Two batch rows per 64-thread block;
// thread i owns h[i] of both rows. Packing is over the REDUCTION dim j:
//   packed weight reg  = (W_hh[i][2q],   W_hh[i][2q+1])  -> direct LDG, 64 regs
//   packed h operand   = (h[2q],         h[2q+1])        -> direct LDS.128
// so no weight duplication and no register spill (R3 lesson: wp[64] dup'd
// packing needed 128 regs, ptxas capped at 96 and spilled to local).
// Accumulator lanes hold (even-j sum, odd-j sum); one horizontal add at end.
// ---------------------------------------------------------------------------
__global__ __launch_bounds__(64, 4) void rnn2_kernel(
    const int*   __restrict__ x32,
    const float* __restrict__ W_hh,
    const float* __restrict__ fc_w,
    const float* __restrict__ fc_b,
    float*       __restrict__ out)
{
    __shared__ int    s_tok[2][SEQ];
    __shared__ float  s_hA[2][HDIM];
    __shared__ float  s_hB[2][HDIM];
    __shared__ float2 s_part[2];

    const int bp = blockIdx.x;            // 0..511
    const int b0 = 2 * bp, b1 = 2 * bp + 1;
    const int i  = threadIdx.x;
    const int flag = g_x64flag;

    // Preload both rows' tokens (handles int32 or int64 source layout)
    for (int t = i; t < SEQ; t += 64) {
        long baseA = (long)b0 * SEQ + t;
        long baseB = (long)b1 * SEQ + t;
        s_tok[0][t] = flag ? x32[2 * baseA] : x32[baseA];
        s_tok[1][t] = flag ? x32[2 * baseB] : x32[baseB];
    }

    // W_hh row i as 32 packed (w[2q], w[2q+1]) regs — natural 128-bit loads.
    unsigned long long wp[HDIM / 2];
    {
        const ulonglong2* wv = (const ulonglong2*)(W_hh + i * HDIM);
        #pragma unroll
        for (int q = 0; q < 16; q++) {
            ulonglong2 u = wv[q];
            wp[2 * q + 0] = u.x;
            wp[2 * q + 1] = u.y;
        }
    }

    s_hA[0][i] = 0.0f;
    s_hB[0][i] = 0.0f;
    __syncthreads();

    float xpA = g_proj[s_tok[0][0] * HDIM + i];
    float xpB = g_proj[s_tok[1][0] * HDIM + i];
    float hA = 0.0f, hB = 0.0f;

    #pragma unroll 1
    for (int t = 0; t < SEQ; t++) {
        const int cur = t & 1, nxt = cur ^ 1;

        unsigned long long aA0, aA1 = 0ULL, aA2 = 0ULL, aA3 = 0ULL;
        unsigned long long aB0, aB1 = 0ULL, aB2 = 0ULL, aB3 = 0ULL;
        asm("mov.b64 %0, {%1, %2};" : "=l"(aA0) : "f"(xpA), "f"(0.0f));
        asm("mov.b64 %0, {%1, %2};" : "=l"(aB0) : "f"(xpB), "f"(0.0f));

        // Prefetch next step's projected rows (wraps harmlessly at t=511)
        int tn = (t + 1) & (SEQ - 1);
        xpA = g_proj[s_tok[0][tn] * HDIM + i];
        xpB = g_proj[s_tok[1][tn] * HDIM + i];

        const ulonglong2* pA = (const ulonglong2*)s_hA[cur];
        const ulonglong2* pB = (const ulonglong2*)s_hB[cur];
        #pragma unroll
        for (int q = 0; q < 16; q += 2) {      // each ulonglong2 = 2 j-pairs
            ulonglong2 uA0 = pA[q], uA1 = pA[q + 1];
            ulonglong2 uB0 = pB[q], uB1 = pB[q + 1];
            FMA2(aA0, uA0.x, wp[2 * q + 0]);
            FMA2(aA1, uA0.y, wp[2 * q + 1]);
            FMA2(aA2, uA1.x, wp[2 * q + 2]);
            FMA2(aA3, uA1.y, wp[2 * q + 3]);
            FMA2(aB0, uB0.x, wp[2 * q + 0]);
            FMA2(aB1, uB0.y, wp[2 * q + 1]);
            FMA2(aB2, uB1.x, wp[2 * q + 2]);
            FMA2(aB3, uB1.y, wp[2 * q + 3]);
        }
        ADD2(aA0, aA1); ADD2(aA2, aA3); ADD2(aA0, aA2);
        ADD2(aB0, aB1); ADD2(aB2, aB3); ADD2(aB0, aB2);

        float eA, oA, eB, oB;
        asm("mov.b64 {%0, %1}, %2;" : "=f"(eA), "=f"(oA) : "l"(aA0));
        asm("mov.b64 {%0, %1}, %2;" : "=f"(eB), "=f"(oB) : "l"(aB0));
        hA = fast_tanh(eA + oA);
        hB = fast_tanh(eB + oB);
        s_hA[nxt][i] = hA;
        s_hB[nxt][i] = hB;
        __syncthreads();
    }

    // fc + sigmoid for both rows
    float f = fc_w[i];
    float vA = hA * f, vB = hB * f;
    #pragma unroll
    for (int off = 16; off; off >>= 1) {
        vA += __shfl_xor_sync(0xffffffff, vA, off);
        vB += __shfl_xor_sync(0xffffffff, vB, off);
    }
    if ((i & 31) == 0) s_part[i >> 5] = make_float2(vA, vB);
    __syncthreads();
    if (i == 0) {
        float bias = fc_b[0];
        float lA = s_part[0].x + s_part[1].x + bias;
        float lB = s_part[0].y + s_part[1].y + bias;
        out[b0] = 1.0f / (1.0f + expf(-lA));
        out[b1] = 1.0f / (1.0f + expf(-lB));
    }
}

// ---------------------------------------------------------------------------
// Launch. Inputs (metadata order): x, emb, W_ih, W_hh, b_ih, b_hh, fc_w, fc_b
// 2 launches/call so ncu -s 5 -c 1 lands on rnn2_kernel.
// ---------------------------------------------------------------------------
extern "C" void kernel_launch(void* const* d_in, const int* in_sizes, int n_in,
                              void* d_out, int out_size)
{
    const int*   x32  = (const int*)  d_in[0];
    const float* emb  = (const float*)d_in[1];
    const float* W_ih = (const float*)d_in[2];
    const float* W_hh = (const float*)d_in[3];
    const float* b_ih = (const float*)d_in[4];
    const float* b_hh = (const float*)d_in[5];
    const float* fc_w = (const float*)d_in[6];
    const float* fc_b = (const float*)d_in[7];
    float* out = (float*)d_out;

    proj_kernel<<<(VOCAB + PROJ_ROWS - 1) / PROJ_ROWS, 256>>>(x32, emb, W_ih, b_ih, b_hh);
    rnn2_kernel<<<BATCH / 2, 64>>>(x32, W_hh, fc_w, fc_b, out);
}

// round 5
// speedup vs baseline: 1.4206x; 1.2243x over previous
#include <cuda_runtime.h>
#include <cuda_bf16.h>
#include <cstdint>

// Problem dims (fixed by the reference)
#define VOCAB 50000
#define EDIM  64
#define HDIM  64
#define BATCH 1024
#define SEQ   512
#define CHUNK 32
#define NCHUNK (SEQ / CHUNK)

// Scratch: projected table proj[v][h] = b_ih[h]+b_hh[h] + sum_e emb[v,e]*W_ih[h,e]
__device__ float g_proj[VOCAB * HDIM];   // 12.8 MB, L2-resident in steady state
__device__ int   g_x64flag;              // 1 if token buffer is int64, 0 if int32

// Fast tanh: tanh(x) = 1 - 2/(1 + exp(2x)). ex2.approx + rcp.approx,
// rel err ~1e-6 (vs ~6e-4 for tanh.approx.f32, which would risk the 1e-3 gate).
__device__ __forceinline__ float fast_tanh(float x) {
    float e, r;
    asm("ex2.approx.f32 %0, %1;" : "=f"(e) : "f"(x * 2.885390081777927f)); // 2/ln2
    asm("rcp.approx.f32 %0, %1;" : "=f"(r) : "f"(e + 1.0f));
    return fmaf(-2.0f, r, 1.0f);
}

#define FMA2(acc, a, b) asm("fma.rn.f32x2 %0, %1, %2, %0;" : "+l"(acc) : "l"(a), "l"(b))
#define ADD2(acc, b)    asm("add.rn.f32x2 %0, %0, %1;"     : "+l"(acc) : "l"(b))

// ---------------------------------------------------------------------------
// Kernel A: build projected embedding table (fuses gather-side GEMM + biases).
// Block 0 warp 0 additionally detects int32-vs-int64 token layout: tokens are
// in [0,50000), so for little-endian int64 every odd 32-bit word is 0.
// ---------------------------------------------------------------------------
#define PROJ_ROWS 32
__global__ __launch_bounds__(256) void proj_kernel(
    const int*   __restrict__ x32,
    const float* __restrict__ emb,
    const float* __restrict__ W_ih,
    const float* __restrict__ b_ih,
    const float* __restrict__ b_hh)
{
    __shared__ float s_w[HDIM * 65];
    __shared__ float s_e[PROJ_ROWS * EDIM];
    __shared__ float s_bias[HDIM];

    const int t  = threadIdx.x;
    const int v0 = blockIdx.x * PROJ_ROWS;

    if (blockIdx.x == 0 && t < 32) {
        unsigned m = __ballot_sync(0xffffffff, x32[2 * t + 1] != 0);
        if (t == 0) g_x64flag = (m == 0u) ? 1 : 0;
    }

    #pragma unroll
    for (int k = 0; k < 16; k++) {
        int idx = t + k * 256;                 // 0..4095
        int hg = idx >> 6, eg = idx & 63;
        s_w[hg * 65 + eg] = W_ih[idx];
    }
    #pragma unroll
    for (int k = 0; k < 8; k++) {
        int idx = t + k * 256;                 // 0..2047
        int r = idx >> 6, e = idx & 63;
        s_e[idx] = (v0 + r < VOCAB) ? emb[(long)(v0 + r) * EDIM + e] : 0.0f;
    }
    if (t < HDIM) s_bias[t] = b_ih[t] + b_hh[t];
    __syncthreads();

    const int h    = t & 63;
    const int rgrp = t >> 6;                   // 0..3
    #pragma unroll
    for (int k = 0; k < 8; k++) {
        int r = rgrp + 4 * k;                  // 0..31
        if (v0 + r >= VOCAB) break;
        float acc = s_bias[h];
        #pragma unroll
        for (int e = 0; e < EDIM; e++)
            acc += s_e[r * EDIM + e] * s_w[h * 65 + e];
        g_proj[(v0 + r) * HDIM + h] = acc;
    }
}

// ---------------------------------------------------------------------------
// Kernel B: warp-autonomous recurrence. One warp per batch row; lane t owns
// h[2t], h[2t+1]; h broadcast via warp-private smem + __syncwarp only (no
// __syncthreads in the hot loop). xp (projected embedding per step) is staged
// in chunks of 32 steps into double-buffered smem with batched MLP=16 gathers
// issued a full chunk ahead -> no exposed L2 latency in the step loop.
// Weights: lane t keeps W_hh rows 2t and 2t+1 as j-pair-packed 64-bit regs.
// ---------------------------------------------------------------------------
__global__ __launch_bounds__(64, 4) void rnn_warp_kernel(
    const int*   __restrict__ x32,
    const float* __restrict__ W_hh,
    const float* __restrict__ fc_w,
    const float* __restrict__ fc_b,
    float*       __restrict__ out)
{
    __shared__ int   s_tok[2][SEQ];                 // 4 KB
    __shared__ float s_h[2][2][HDIM];               // [warp][buf][h]  1 KB
    __shared__ float s_xp[2][2][CHUNK * HDIM];      // [warp][buf][s*64+h]  32 KB

    const int w    = threadIdx.x >> 5;              // warp in block: 0/1
    const int lane = threadIdx.x & 31;
    const int row  = blockIdx.x * 2 + w;
    const int flag = g_x64flag;

    // Tokens for this row (handles int32 or int64 source layout)
    for (int k = lane; k < SEQ; k += 32) {
        long base = (long)row * SEQ + k;
        s_tok[w][k] = flag ? x32[2 * base] : x32[base];
    }
    __syncwarp();

    // Weights: rows 2*lane and 2*lane+1, packed over j-pairs (128 regs total)
    unsigned long long w0[HDIM / 2], w1[HDIM / 2];
    {
        const ulonglong2* a = (const ulonglong2*)(W_hh + (2 * lane)     * HDIM);
        const ulonglong2* b = (const ulonglong2*)(W_hh + (2 * lane + 1) * HDIM);
        #pragma unroll
        for (int q = 0; q < 16; q++) {
            ulonglong2 u = a[q]; w0[2 * q] = u.x; w0[2 * q + 1] = u.y;
            ulonglong2 v = b[q]; w1[2 * q] = v.x; w1[2 * q + 1] = v.y;
        }
    }

    // h init
    *(float2*)&s_h[w][0][2 * lane] = make_float2(0.0f, 0.0f);

    // Stage chunk 0 into xp buffer 0. Task id = lane + 32m: step = id>>4,
    // float4-group = id&15 -> 16 coalesced LDG.128 per lane, MLP=16.
    #pragma unroll
    for (int m = 0; m < 16; m++) {
        int id = lane + 32 * m;
        int st = id >> 4, gp = id & 15;
        int tok = s_tok[w][st];
        float4 v = *(const float4*)(g_proj + tok * HDIM + gp * 4);
        *(float4*)&s_xp[w][0][st * HDIM + gp * 4] = v;
    }
    __syncwarp();

    int hbuf = 0;
    float hv0 = 0.0f, hv1 = 0.0f;

    #pragma unroll 1
    for (int c = 0; c < NCHUNK; c++) {
        const int xbuf = c & 1;
        // Prefetch next chunk into the other buffer (consumed >= 32 steps later)
        if (c + 1 < NCHUNK) {
            #pragma unroll
            for (int m = 0; m < 16; m++) {
                int id = lane + 32 * m;
                int st = id >> 4, gp = id & 15;
                int tok = s_tok[w][(c + 1) * CHUNK + st];
                float4 v = *(const float4*)(g_proj + tok * HDIM + gp * 4);
                *(float4*)&s_xp[w][xbuf ^ 1][st * HDIM + gp * 4] = v;
            }
        }

        #pragma unroll 4
        for (int s = 0; s < CHUNK; s++) {
            float2 xp = *(const float2*)&s_xp[w][xbuf][s * HDIM + 2 * lane];

            unsigned long long a00, a01 = 0ULL, a02 = 0ULL, a03 = 0ULL;
            unsigned long long a10, a11 = 0ULL, a12 = 0ULL, a13 = 0ULL;
            asm("mov.b64 %0, {%1, %2};" : "=l"(a00) : "f"(xp.x), "f"(0.0f));
            asm("mov.b64 %0, {%1, %2};" : "=l"(a10) : "f"(xp.y), "f"(0.0f));

            const ulonglong2* hp = (const ulonglong2*)s_h[w][hbuf];
            #pragma unroll
            for (int q = 0; q < 16; q += 2) {       // 16 LDS.128 broadcasts
                ulonglong2 u0 = hp[q], u1 = hp[q + 1];
                FMA2(a00, u0.x, w0[2 * q + 0]); FMA2(a01, u0.y, w0[2 * q + 1]);
                FMA2(a02, u1.x, w0[2 * q + 2]); FMA2(a03, u1.y, w0[2 * q + 3]);
                FMA2(a10, u0.x, w1[2 * q + 0]); FMA2(a11, u0.y, w1[2 * q + 1]);
                FMA2(a12, u1.x, w1[2 * q + 2]); FMA2(a13, u1.y, w1[2 * q + 3]);
            }
            ADD2(a00, a01); ADD2(a02, a03); ADD2(a00, a02);
            ADD2(a10, a11); ADD2(a12, a13); ADD2(a10, a12);

            float e0, o0, e1, o1;
            asm("mov.b64 {%0, %1}, %2;" : "=f"(e0), "=f"(o0) : "l"(a00));
            asm("mov.b64 {%0, %1}, %2;" : "=f"(e1), "=f"(o1) : "l"(a10));
            hv0 = fast_tanh(e0 + o0);
            hv1 = fast_tanh(e1 + o1);
            *(float2*)&s_h[w][hbuf ^ 1][2 * lane] = make_float2(hv0, hv1);
            hbuf ^= 1;
            __syncwarp();
        }
    }

    // fc + sigmoid: logit = sum_i h[i]*fc_w[i] + fc_b[0]
    float2 f = *(const float2*)(fc_w + 2 * lane);
    float v = hv0 * f.x + hv1 * f.y;
    #pragma unroll
    for (int off = 16; off; off >>= 1)
        v += __shfl_xor_sync(0xffffffff, v, off);
    if (lane == 0)
        out[row] = 1.0f / (1.0f + expf(-(v + fc_b[0])));
}

// ---------------------------------------------------------------------------
// Launch. Inputs (metadata order): x, emb, W_ih, W_hh, b_ih, b_hh, fc_w, fc_b
// 2 launches/call so ncu -s 5 -c 1 lands on rnn_warp_kernel.
// ---------------------------------------------------------------------------
extern "C" void kernel_launch(void* const* d_in, const int* in_sizes, int n_in,
                              void* d_out, int out_size)
{
    const int*   x32  = (const int*)  d_in[0];
    const float* emb  = (const float*)d_in[1];
    const float* W_ih = (const float*)d_in[2];
    const float* W_hh = (const float*)d_in[3];
    const float* b_ih = (const float*)d_in[4];
    const float* b_hh = (const float*)d_in[5];
    const float* fc_w = (const float*)d_in[6];
    const float* fc_b = (const float*)d_in[7];
    float* out = (float*)d_out;

    proj_kernel<<<(VOCAB + PROJ_ROWS - 1) / PROJ_ROWS, 256>>>(x32, emb, W_ih, b_ih, b_hh);
    rnn_warp_kernel<<<BATCH / 2, 64>>>(x32, W_hh, fc_w, fc_b, out);
}

// round 6
// speedup vs baseline: 1.5466x; 1.0887x over previous
#include <cuda_runtime.h>
#include <cuda_bf16.h>
#include <cstdint>

// Problem dims (fixed by the reference)
#define VOCAB 50000
#define EDIM  64
#define HDIM  64
#define BATCH 1024
#define SEQ   512
#define CHUNK 32
#define NCHUNK (SEQ / CHUNK)

// Scratch: projected table proj[v][h] = b_ih[h]+b_hh[h] + sum_e emb[v,e]*W_ih[h,e]
__device__ float g_proj[VOCAB * HDIM];   // 12.8 MB, L2-resident in steady state
__device__ int   g_x64flag;              // 1 if token buffer is int64, 0 if int32

// Fast tanh: tanh(x) = 1 - 2/(1 + exp(2x)). ex2.approx + rcp.approx,
// rel err ~1e-6 (vs ~6e-4 for tanh.approx.f32, which would risk the 1e-3 gate).
__device__ __forceinline__ float fast_tanh(float x) {
    float e, r;
    asm("ex2.approx.f32 %0, %1;" : "=f"(e) : "f"(x * 2.885390081777927f)); // 2/ln2
    asm("rcp.approx.f32 %0, %1;" : "=f"(r) : "f"(e + 1.0f));
    return fmaf(-2.0f, r, 1.0f);
}

#define FMA2(acc, a, b) asm("fma.rn.f32x2 %0, %1, %2, %0;" : "+l"(acc) : "l"(a), "l"(b))
#define ADD2(acc, b)    asm("add.rn.f32x2 %0, %0, %1;"     : "+l"(acc) : "l"(b))

__device__ __forceinline__ uint32_t smem_u32(const void* p) {
    uint32_t a;
    asm("{ .reg .u64 t; cvta.to.shared.u64 t, %1; cvt.u32.u64 %0, t; }" : "=r"(a) : "l"(p));
    return a;
}
// 16B async copy global->shared (LDGSTS): no register staging, no stall.
#define CP_ASYNC16(dst_u32, src_ptr) \
    asm volatile("cp.async.cg.shared.global [%0], [%1], 16;" :: "r"(dst_u32), "l"(src_ptr))
#define CP_COMMIT() asm volatile("cp.async.commit_group;" ::: "memory")
#define CP_WAIT0()  asm volatile("cp.async.wait_group 0;"  ::: "memory")

// ---------------------------------------------------------------------------
// Kernel A: build projected embedding table (fuses gather-side GEMM + biases).
// Block 0 warp 0 additionally detects int32-vs-int64 token layout: tokens are
// in [0,50000), so for little-endian int64 every odd 32-bit word is 0.
// ---------------------------------------------------------------------------
#define PROJ_ROWS 32
__global__ __launch_bounds__(256) void proj_kernel(
    const int*   __restrict__ x32,
    const float* __restrict__ emb,
    const float* __restrict__ W_ih,
    const float* __restrict__ b_ih,
    const float* __restrict__ b_hh)
{
    __shared__ float s_w[HDIM * 65];
    __shared__ float s_e[PROJ_ROWS * EDIM];
    __shared__ float s_bias[HDIM];

    const int t  = threadIdx.x;
    const int v0 = blockIdx.x * PROJ_ROWS;

    if (blockIdx.x == 0 && t < 32) {
        unsigned m = __ballot_sync(0xffffffff, x32[2 * t + 1] != 0);
        if (t == 0) g_x64flag = (m == 0u) ? 1 : 0;
    }

    #pragma unroll
    for (int k = 0; k < 16; k++) {
        int idx = t + k * 256;                 // 0..4095
        int hg = idx >> 6, eg = idx & 63;
        s_w[hg * 65 + eg] = W_ih[idx];
    }
    #pragma unroll
    for (int k = 0; k < 8; k++) {
        int idx = t + k * 256;                 // 0..2047
        int r = idx >> 6, e = idx & 63;
        s_e[idx] = (v0 + r < VOCAB) ? emb[(long)(v0 + r) * EDIM + e] : 0.0f;
    }
    if (t < HDIM) s_bias[t] = b_ih[t] + b_hh[t];
    __syncthreads();

    const int h    = t & 63;
    const int rgrp = t >> 6;                   // 0..3
    #pragma unroll
    for (int k = 0; k < 8; k++) {
        int r = rgrp + 4 * k;                  // 0..31
        if (v0 + r >= VOCAB) break;
        float acc = s_bias[h];
        #pragma unroll
        for (int e = 0; e < EDIM; e++)
            acc += s_e[r * EDIM + e] * s_w[h * 65 + e];
        g_proj[(v0 + r) * HDIM + h] = acc;
    }
}

// ---------------------------------------------------------------------------
// Kernel B: TWO independent recurrence chains per warp (ILP, not TLP).
// One warp (= one 32-thread block) owns batch rows b0, b1. Lane t owns
// h[2t], h[2t+1] of BOTH rows; the two rows' per-step chains (LDS h -> FMA ->
// tanh -> STS) are data-independent, so row B's FMAs issue inside row A's
// latency shadows. One __syncwarp per step. xp staged per chunk of 32 steps
// via cp.async (2 LDGSTS per step, spread over the chunk; no boundary bubble).
// ---------------------------------------------------------------------------
__global__ __launch_bounds__(32, 8) void rnn_ilp2_kernel(
    const int*   __restrict__ x32,
    const float* __restrict__ W_hh,
    const float* __restrict__ fc_w,
    const float* __restrict__ fc_b,
    float*       __restrict__ out)
{
    __shared__ int   s_tok[2][SEQ];                 // [row][t]      4 KB
    __shared__ float s_h[2][2][HDIM];               // [row][buf][h] 1 KB
    __shared__ float s_xp[2][2][CHUNK * HDIM];      // [row][buf]   32 KB

    const int lane = threadIdx.x;
    const int b0 = blockIdx.x * 2, b1 = b0 + 1;
    const int flag = g_x64flag;

    // Tokens for both rows (handles int32 or int64 source layout)
    for (int k = lane; k < SEQ; k += 32) {
        long a = (long)b0 * SEQ + k;
        long b = (long)b1 * SEQ + k;
        s_tok[0][k] = flag ? x32[2 * a] : x32[a];
        s_tok[1][k] = flag ? x32[2 * b] : x32[b];
    }
    __syncwarp();

    // Weights: rows 2*lane and 2*lane+1, packed over j-pairs (128 regs total)
    unsigned long long w0[HDIM / 2], w1[HDIM / 2];
    {
        const ulonglong2* a = (const ulonglong2*)(W_hh + (2 * lane)     * HDIM);
        const ulonglong2* b = (const ulonglong2*)(W_hh + (2 * lane + 1) * HDIM);
        #pragma unroll
        for (int q = 0; q < 16; q++) {
            ulonglong2 u = a[q]; w0[2 * q] = u.x; w0[2 * q + 1] = u.y;
            ulonglong2 v = b[q]; w1[2 * q] = v.x; w1[2 * q + 1] = v.y;
        }
    }

    *(float2*)&s_h[0][0][2 * lane] = make_float2(0.0f, 0.0f);
    *(float2*)&s_h[1][0][2 * lane] = make_float2(0.0f, 0.0f);

    // Stage chunk 0 for both rows. Task id = lane + 32m: step = id>>4,
    // float4-group = id&15 -> 16 coalesced 16B copies per lane per row.
    #pragma unroll
    for (int m = 0; m < 16; m++) {
        int id = lane + 32 * m;
        int st = id >> 4, gp = id & 15;
        CP_ASYNC16(smem_u32(&s_xp[0][0][st * HDIM + gp * 4]),
                   g_proj + s_tok[0][st] * HDIM + gp * 4);
        CP_ASYNC16(smem_u32(&s_xp[1][0][st * HDIM + gp * 4]),
                   g_proj + s_tok[1][st] * HDIM + gp * 4);
    }
    CP_COMMIT(); CP_WAIT0();
    __syncwarp();

    int hbuf = 0;
    float hA0 = 0.0f, hA1 = 0.0f, hB0 = 0.0f, hB1 = 0.0f;

    #pragma unroll 1
    for (int c = 0; c < NCHUNK; c++) {
        const int xbuf = c & 1;
        const bool more = (c + 1 < NCHUNK);

        #pragma unroll 2
        for (int s = 0; s < CHUNK; s++) {
            // Spread next-chunk prefetch: 2 LDGSTS per step for s in [0,16)
            if (more && s < 16) {
                int id = lane + 32 * s;
                int st = id >> 4, gp = id & 15;
                CP_ASYNC16(smem_u32(&s_xp[0][xbuf ^ 1][st * HDIM + gp * 4]),
                           g_proj + s_tok[0][(c + 1) * CHUNK + st] * HDIM + gp * 4);
                CP_ASYNC16(smem_u32(&s_xp[1][xbuf ^ 1][st * HDIM + gp * 4]),
                           g_proj + s_tok[1][(c + 1) * CHUNK + st] * HDIM + gp * 4);
            }

            float2 xpA = *(const float2*)&s_xp[0][xbuf][s * HDIM + 2 * lane];
            float2 xpB = *(const float2*)&s_xp[1][xbuf][s * HDIM + 2 * lane];

            unsigned long long a00, a01 = 0ULL, a02 = 0ULL, a03 = 0ULL;
            unsigned long long a10, a11 = 0ULL, a12 = 0ULL, a13 = 0ULL;
            unsigned long long c00, c01 = 0ULL, c02 = 0ULL, c03 = 0ULL;
            unsigned long long c10, c11 = 0ULL, c12 = 0ULL, c13 = 0ULL;
            asm("mov.b64 %0, {%1, %2};" : "=l"(a00) : "f"(xpA.x), "f"(0.0f));
            asm("mov.b64 %0, {%1, %2};" : "=l"(a10) : "f"(xpA.y), "f"(0.0f));
            asm("mov.b64 %0, {%1, %2};" : "=l"(c00) : "f"(xpB.x), "f"(0.0f));
            asm("mov.b64 %0, {%1, %2};" : "=l"(c10) : "f"(xpB.y), "f"(0.0f));

            const ulonglong2* hpA = (const ulonglong2*)s_h[0][hbuf];
            const ulonglong2* hpB = (const ulonglong2*)s_h[1][hbuf];
            #pragma unroll
            for (int q = 0; q < 16; q += 2) {
                ulonglong2 uA0 = hpA[q], uA1 = hpA[q + 1];
                ulonglong2 uB0 = hpB[q], uB1 = hpB[q + 1];
                FMA2(a00, uA0.x, w0[2 * q + 0]); FMA2(a01, uA0.y, w0[2 * q + 1]);
                FMA2(a02, uA1.x, w0[2 * q + 2]); FMA2(a03, uA1.y, w0[2 * q + 3]);
                FMA2(a10, uA0.x, w1[2 * q + 0]); FMA2(a11, uA0.y, w1[2 * q + 1]);
                FMA2(a12, uA1.x, w1[2 * q + 2]); FMA2(a13, uA1.y, w1[2 * q + 3]);
                FMA2(c00, uB0.x, w0[2 * q + 0]); FMA2(c01, uB0.y, w0[2 * q + 1]);
                FMA2(c02, uB1.x, w0[2 * q + 2]); FMA2(c03, uB1.y, w0[2 * q + 3]);
                FMA2(c10, uB0.x, w1[2 * q + 0]); FMA2(c11, uB0.y, w1[2 * q + 1]);
                FMA2(c12, uB1.x, w1[2 * q + 2]); FMA2(c13, uB1.y, w1[2 * q + 3]);
            }
            ADD2(a00, a01); ADD2(a02, a03); ADD2(a00, a02);
            ADD2(a10, a11); ADD2(a12, a13); ADD2(a10, a12);
            ADD2(c00, c01); ADD2(c02, c03); ADD2(c00, c02);
            ADD2(c10, c11); ADD2(c12, c13); ADD2(c10, c12);

            float e0, o0, e1, o1, e2, o2, e3, o3;
            asm("mov.b64 {%0, %1}, %2;" : "=f"(e0), "=f"(o0) : "l"(a00));
            asm("mov.b64 {%0, %1}, %2;" : "=f"(e1), "=f"(o1) : "l"(a10));
            asm("mov.b64 {%0, %1}, %2;" : "=f"(e2), "=f"(o2) : "l"(c00));
            asm("mov.b64 {%0, %1}, %2;" : "=f"(e3), "=f"(o3) : "l"(c10));
            hA0 = fast_tanh(e0 + o0);
            hA1 = fast_tanh(e1 + o1);
            hB0 = fast_tanh(e2 + o2);
            hB1 = fast_tanh(e3 + o3);
            *(float2*)&s_h[0][hbuf ^ 1][2 * lane] = make_float2(hA0, hA1);
            *(float2*)&s_h[1][hbuf ^ 1][2 * lane] = make_float2(hB0, hB1);
            hbuf ^= 1;
            __syncwarp();
        }
        // All of next chunk's LDGSTS were issued in steps 0..15; make visible.
        CP_COMMIT(); CP_WAIT0();
        __syncwarp();
    }

    // fc + sigmoid for both rows (warp-local shuffle reduce)
    float2 f = *(const float2*)(fc_w + 2 * lane);
    float vA = hA0 * f.x + hA1 * f.y;
    float vB = hB0 * f.x + hB1 * f.y;
    #pragma unroll
    for (int off = 16; off; off >>= 1) {
        vA += __shfl_xor_sync(0xffffffff, vA, off);
        vB += __shfl_xor_sync(0xffffffff, vB, off);
    }
    if (lane == 0) {
        float bias = fc_b[0];
        out[b0] = 1.0f / (1.0f + expf(-(vA + bias)));
        out[b1] = 1.0f / (1.0f + expf(-(vB + bias)));
    }
}

// ---------------------------------------------------------------------------
// Launch. Inputs (metadata order): x, emb, W_ih, W_hh, b_ih, b_hh, fc_w, fc_b
// 2 launches/call so ncu -s 5 -c 1 lands on rnn_ilp2_kernel.
// ---------------------------------------------------------------------------
extern "C" void kernel_launch(void* const* d_in, const int* in_sizes, int n_in,
                              void* d_out, int out_size)
{
    const int*   x32  = (const int*)  d_in[0];
    const float* emb  = (const float*)d_in[1];
    const float* W_ih = (const float*)d_in[2];
    const float* W_hh = (const float*)d_in[3];
    const float* b_ih = (const float*)d_in[4];
    const float* b_hh = (const float*)d_in[5];
    const float* fc_w = (const float*)d_in[6];
    const float* fc_b = (const float*)d_in[7];
    float* out = (float*)d_out;

    proj_kernel<<<(VOCAB + PROJ_ROWS - 1) / PROJ_ROWS, 256>>>(x32, emb, W_ih, b_ih, b_hh);
    rnn_ilp2_kernel<<<BATCH / 2, 32>>>(x32, W_hh, fc_w, fc_b, out);
}